// round 17
// baseline (speedup 1.0000x reference)
// R17: R16 with the GEMM made persistent: 444 CTAs (3/SM x 148) loop over
// all 1564 tiles, eliminating the 3.52-wave quantization tail and the
// per-wave transition overhead. Tile order stays N-fastest (x slab + W
// L2-resident). All other kernels + fork/join launcher identical to R16.
#include <cuda_runtime.h>
#include <math.h>
#include <stdint.h>

#define NN 50000       // nodes
#define KD 512         // input feature dim
#define FO 256         // output classes
#define ER 850000      // edges: 800000 random + 50000 self loops

// -------- scratch (device globals; no allocation allowed) --------
__device__ __align__(16) float g_h[(size_t)NN * FO];   // h = x@W (51.2 MB)
__device__ float g_srow[NN];
__device__ float g_scol[NN];
__device__ int   g_cnt[NN];      // per-row degree
__device__ int   g_off[NN];      // CSR row start
__device__ int   g_cur[NN];      // fill cursor
__device__ int   g_ecol[ER];     // CSR: source node of each edge
#define SCAN_B 196               // scan blocks (196*256 = 50176 >= NN)
__device__ int   g_part[SCAN_B]; // per-block partial sums

// ---- packed f32x2 helpers ----
__device__ __forceinline__ uint64_t pack2(float lo, float hi) {
    uint64_t p;
    asm("mov.b64 %0, {%1, %2};" : "=l"(p) : "f"(lo), "f"(hi));
    return p;
}
__device__ __forceinline__ void unpack2(uint64_t p, float &lo, float &hi) {
    asm("mov.b64 {%0, %1}, %2;" : "=f"(lo), "=f"(hi) : "l"(p));
}
__device__ __forceinline__ void fma2(uint64_t &d, uint64_t a, uint64_t b) {
    asm("fma.rn.f32x2 %0, %1, %2, %0;" : "+l"(d) : "l"(a), "l"(b));
}

// ============ K0: zero scores + degree counters ============
__global__ __launch_bounds__(256) void init_kernel() {
    int i = blockIdx.x * blockDim.x + threadIdx.x;
    if (i < NN) {
        g_srow[i] = 0.f;
        g_scol[i] = 0.f;
        g_cnt[i]  = 0;
    }
}

// ====== K1: persistent SGEMM h = x @ W (f32x2, double-buffered) + fused scores ======
#define BM 128
#define BN 64
#define BK 16
#define TM 8
#define TN 4
#define AK_STRIDE 130   // floats per k-row (even -> LDS.64 aligned; %32=2 -> banks spread)
#define NCHUNK (KD / BK)
#define MTILES ((NN + BM - 1) / BM)      // 391
#define NTILES (FO / BN)                 // 4
#define TOT_TILES (MTILES * NTILES)      // 1564
#define GEMM_CTAS 444                    // 148 SMs x 3 resident

__global__ __launch_bounds__(256) void gemm_kernel(const float* __restrict__ x,
                                                   const float* __restrict__ W,
                                                   const float* __restrict__ avec) {
    __shared__ __align__(16) float Ask[2][BK * AK_STRIDE];   // k-major: Ask[buf][k][m]
    __shared__ __align__(16) float Bs[2][BK][BN];
    __shared__ __align__(16) float A1s[BN];                  // a[n0 .. n0+63]
    __shared__ __align__(16) float A2s[BN];                  // a[FO+n0 .. FO+n0+63]

    const int tid = threadIdx.x;
    const int tx = tid & 15;        // N direction (4 cols each)
    const int ty = tid >> 4;        // M direction (8 rows each)

    const int arow = tid >> 1;             // 0..127 (two threads per row)
    const int ak4  = (tid & 1) * 2;        // k-group 0..1 / 2..3
    const int brow = tid >> 4;             // 0..15 (k)
    const int bc4  = tid & 15;

    for (int t = blockIdx.x; t < TOT_TILES; t += GEMM_CTAS) {
        const int n0 = (t & 3) * BN;       // N fastest -> L2 reuse of x slab + W
        const int m0 = (t >> 2) * BM;
        const bool aok = (m0 + arow) < NN;

        __syncthreads();   // protect A1s/A2s + smem from previous tile's readers

        uint64_t acc[TM / 2][TN];
#pragma unroll
        for (int i = 0; i < TM / 2; i++)
#pragma unroll
            for (int j = 0; j < TN; j++) acc[i][j] = pack2(0.f, 0.f);

        // stage attention-vector slices for the fused score epilogue
        if (tid < BN)             A1s[tid]      = avec[n0 + tid];
        else if (tid < 2 * BN)    A2s[tid - BN] = avec[FO + n0 + tid - BN];

        // prologue: load chunk 0 into buffer 0
        {
            const float* srcA = x + (size_t)(m0 + arow) * KD + ak4 * 4;
#pragma unroll
            for (int g = 0; g < 2; g++) {
                float4 v = aok ? *(const float4*)(srcA + g * 4)
                               : make_float4(0.f, 0.f, 0.f, 0.f);
                int kb = (ak4 + g) * 4;
                Ask[0][(kb + 0) * AK_STRIDE + arow] = v.x;
                Ask[0][(kb + 1) * AK_STRIDE + arow] = v.y;
                Ask[0][(kb + 2) * AK_STRIDE + arow] = v.z;
                Ask[0][(kb + 3) * AK_STRIDE + arow] = v.w;
            }
            *(float4*)&Bs[0][brow][bc4 * 4] =
                *(const float4*)&W[(size_t)brow * FO + n0 + bc4 * 4];
        }
        __syncthreads();

        for (int c = 0; c < NCHUNK; c++) {
            int buf = c & 1;
            // ---- prefetch chunk c+1 into the other buffer ----
            if (c + 1 < NCHUNK) {
                int nxt = buf ^ 1;
                int k0 = (c + 1) * BK;
                const float* srcA = x + (size_t)(m0 + arow) * KD + k0 + ak4 * 4;
#pragma unroll
                for (int g = 0; g < 2; g++) {
                    float4 v = aok ? *(const float4*)(srcA + g * 4)
                                   : make_float4(0.f, 0.f, 0.f, 0.f);
                    int kb = (ak4 + g) * 4;
                    Ask[nxt][(kb + 0) * AK_STRIDE + arow] = v.x;
                    Ask[nxt][(kb + 1) * AK_STRIDE + arow] = v.y;
                    Ask[nxt][(kb + 2) * AK_STRIDE + arow] = v.z;
                    Ask[nxt][(kb + 3) * AK_STRIDE + arow] = v.w;
                }
                *(float4*)&Bs[nxt][brow][bc4 * 4] =
                    *(const float4*)&W[(size_t)(k0 + brow) * FO + n0 + bc4 * 4];
            }
            // ---- compute on current buffer ----
#pragma unroll
            for (int kk = 0; kk < BK; kk++) {
                uint64_t ap[TM / 2];
#pragma unroll
                for (int i = 0; i < TM / 2; i++)
                    ap[i] = *(const uint64_t*)&Ask[buf][kk * AK_STRIDE + ty * TM + 2 * i];
                float4 b4 = *(float4*)&Bs[buf][kk][tx * TN];
                uint64_t bd[TN] = { pack2(b4.x, b4.x), pack2(b4.y, b4.y),
                                    pack2(b4.z, b4.z), pack2(b4.w, b4.w) };
#pragma unroll
                for (int i = 0; i < TM / 2; i++)
#pragma unroll
                    for (int j = 0; j < TN; j++)
                        fma2(acc[i][j], ap[i], bd[j]);
            }
            __syncthreads();
        }

        // ---- epilogue: write h + fused partial score dots ----
#pragma unroll
        for (int i = 0; i < TM / 2; i++) {
            float lo[TN], hi[TN];
#pragma unroll
            for (int j = 0; j < TN; j++) unpack2(acc[i][j], lo[j], hi[j]);
            int gr0 = m0 + ty * TM + 2 * i;
            if (gr0 < NN)
                *(float4*)&g_h[(size_t)gr0 * FO + n0 + tx * TN] =
                    make_float4(lo[0], lo[1], lo[2], lo[3]);
            if (gr0 + 1 < NN)
                *(float4*)&g_h[(size_t)(gr0 + 1) * FO + n0 + tx * TN] =
                    make_float4(hi[0], hi[1], hi[2], hi[3]);

            float sl1 = 0.f, sl2 = 0.f, sh1 = 0.f, sh2 = 0.f;
#pragma unroll
            for (int j = 0; j < TN; j++) {
                float a1 = A1s[tx * TN + j];
                float a2 = A2s[tx * TN + j];
                sl1 = fmaf(lo[j], a1, sl1);
                sl2 = fmaf(lo[j], a2, sl2);
                sh1 = fmaf(hi[j], a1, sh1);
                sh2 = fmaf(hi[j], a2, sh2);
            }
#pragma unroll
            for (int o = 8; o; o >>= 1) {   // xor of bits 0..3 stays in 16-lane group
                sl1 += __shfl_xor_sync(0xFFFFFFFFu, sl1, o);
                sl2 += __shfl_xor_sync(0xFFFFFFFFu, sl2, o);
                sh1 += __shfl_xor_sync(0xFFFFFFFFu, sh1, o);
                sh2 += __shfl_xor_sync(0xFFFFFFFFu, sh2, o);
            }
            if (tx == 0) {
                if (gr0 < NN) {
                    atomicAdd(&g_srow[gr0], sl1);
                    atomicAdd(&g_scol[gr0], sl2);
                }
                if (gr0 + 1 < NN) {
                    atomicAdd(&g_srow[gr0 + 1], sh1);
                    atomicAdd(&g_scol[gr0 + 1], sh2);
                }
            }
        }
    }
}

// ============ K3: degree histogram ============
__global__ __launch_bounds__(256) void hist_kernel(const int* __restrict__ row) {
    int i = blockIdx.x * blockDim.x + threadIdx.x;
    if (i >= ER) return;
    atomicAdd(&g_cnt[row[i]], 1);
}

// ============ K4a/b/c: 3-pass parallel exclusive scan over g_cnt ============
__global__ __launch_bounds__(256) void scan_reduce() {
    __shared__ __align__(16) int sh[256];
    int t = threadIdx.x;
    int idx = blockIdx.x * 256 + t;
    int v = (idx < NN) ? g_cnt[idx] : 0;
    sh[t] = v;
    __syncthreads();
#pragma unroll
    for (int s = 128; s; s >>= 1) {
        if (t < s) sh[t] += sh[t + s];
        __syncthreads();
    }
    if (t == 0) g_part[blockIdx.x] = sh[0];
}

__global__ __launch_bounds__(256) void scan_partials() {
    __shared__ __align__(16) int sh[256];
    int t = threadIdx.x;
    sh[t] = (t < SCAN_B) ? g_part[t] : 0;
    __syncthreads();
#pragma unroll
    for (int d = 1; d < 256; d <<= 1) {
        int v = (t >= d) ? sh[t - d] : 0;
        __syncthreads();
        sh[t] += v;
        __syncthreads();
    }
    if (t < SCAN_B) g_part[t] = (t > 0) ? sh[t - 1] : 0;   // exclusive
}

__global__ __launch_bounds__(256) void scan_write() {
    __shared__ __align__(16) int sh[256];
    int t = threadIdx.x;
    int idx = blockIdx.x * 256 + t;
    int v = (idx < NN) ? g_cnt[idx] : 0;
    sh[t] = v;
    __syncthreads();
#pragma unroll
    for (int d = 1; d < 256; d <<= 1) {
        int u = (t >= d) ? sh[t - d] : 0;
        __syncthreads();
        sh[t] += u;
        __syncthreads();
    }
    if (idx < NN) {
        int off = g_part[blockIdx.x] + sh[t] - v;   // exclusive = inclusive - self
        g_off[idx] = off;
        g_cur[idx] = off;
    }
}

// ============ K5: CSR structure fill (side stream) ============
__global__ __launch_bounds__(256) void fill_kernel(const int* __restrict__ row,
                                                   const int* __restrict__ col) {
    int i = blockIdx.x * blockDim.x + threadIdx.x;
    if (i >= ER) return;
    int r = row[i];
    int pos = atomicAdd(&g_cur[r], 1);
    g_ecol[pos] = col[i];
}

// ==== K6: gather-reduce with inline coefficients + ELU + log_softmax ====
__device__ __forceinline__ float wred_max(float v) {
#pragma unroll
    for (int o = 16; o; o >>= 1) v = fmaxf(v, __shfl_xor_sync(0xFFFFFFFFu, v, o));
    return v;
}
__device__ __forceinline__ float wred_sum(float v) {
#pragma unroll
    for (int o = 16; o; o >>= 1) v += __shfl_xor_sync(0xFFFFFFFFu, v, o);
    return v;
}
__device__ __forceinline__ float coeff(float srn, float sc) {
    float z = srn + sc;
    float l = z > 0.f ? z : 0.2f * z;        // leaky_relu, slope 0.2
    return expf(-l);
}

__global__ __launch_bounds__(256) void gather_final(float* __restrict__ out) {
    const int t     = threadIdx.x;
    const int ng    = t >> 6;            // node group 0..3 (2 warps each)
    const int s     = t & 63;            // sub-thread within node
    const int lane  = t & 31;
    const int warp  = t >> 5;            // node ng owns warps 2ng, 2ng+1
    const int n     = blockIdx.x * 4 + ng;   // NN % 4 == 0

    __shared__ __align__(16) float smax[8];
    __shared__ __align__(16) float ssum[8];

    const int start = g_off[n];
    const int deg   = g_cnt[n];          // >= 1 (self loop)
    const int fbase = s * 4;             // features s*4 .. s*4+3
    const float srn = g_srow[n];         // uniform per node group

    float4 acc0 = make_float4(0.f, 0.f, 0.f, 0.f);
    float4 acc1 = make_float4(0.f, 0.f, 0.f, 0.f);
    float rs = 0.f;

    int j = 0;
    for (; j + 4 <= deg; j += 4) {
        int   c0 = g_ecol[start + j];        // warp-uniform -> broadcast loads
        int   c1 = g_ecol[start + j + 1];
        int   c2 = g_ecol[start + j + 2];
        int   c3 = g_ecol[start + j + 3];
        float e0 = coeff(srn, g_scol[c0]);
        float e1 = coeff(srn, g_scol[c1]);
        float e2 = coeff(srn, g_scol[c2]);
        float e3 = coeff(srn, g_scol[c3]);
        float4 h0 = *(const float4*)&g_h[(size_t)c0 * FO + fbase];
        float4 h1 = *(const float4*)&g_h[(size_t)c1 * FO + fbase];
        float4 h2 = *(const float4*)&g_h[(size_t)c2 * FO + fbase];
        float4 h3 = *(const float4*)&g_h[(size_t)c3 * FO + fbase];
        acc0.x = fmaf(e0, h0.x, acc0.x); acc0.y = fmaf(e0, h0.y, acc0.y);
        acc0.z = fmaf(e0, h0.z, acc0.z); acc0.w = fmaf(e0, h0.w, acc0.w);
        acc1.x = fmaf(e1, h1.x, acc1.x); acc1.y = fmaf(e1, h1.y, acc1.y);
        acc1.z = fmaf(e1, h1.z, acc1.z); acc1.w = fmaf(e1, h1.w, acc1.w);
        acc0.x = fmaf(e2, h2.x, acc0.x); acc0.y = fmaf(e2, h2.y, acc0.y);
        acc0.z = fmaf(e2, h2.z, acc0.z); acc0.w = fmaf(e2, h2.w, acc0.w);
        acc1.x = fmaf(e3, h3.x, acc1.x); acc1.y = fmaf(e3, h3.y, acc1.y);
        acc1.z = fmaf(e3, h3.z, acc1.z); acc1.w = fmaf(e3, h3.w, acc1.w);
        rs += (e0 + e1) + (e2 + e3);
    }
    for (; j < deg; j++) {
        int   c0 = g_ecol[start + j];
        float e0 = coeff(srn, g_scol[c0]);
        float4 h0 = *(const float4*)&g_h[(size_t)c0 * FO + fbase];
        acc0.x = fmaf(e0, h0.x, acc0.x); acc0.y = fmaf(e0, h0.y, acc0.y);
        acc0.z = fmaf(e0, h0.z, acc0.z); acc0.w = fmaf(e0, h0.w, acc0.w);
        rs += e0;
    }

    float4 v;
    v.x = (acc0.x + acc1.x) / rs;
    v.y = (acc0.y + acc1.y) / rs;
    v.z = (acc0.z + acc1.z) / rs;
    v.w = (acc0.w + acc1.w) / rs;
    v.x = v.x > 0.f ? v.x : expm1f(v.x);     // ELU (alpha=1)
    v.y = v.y > 0.f ? v.y : expm1f(v.y);
    v.z = v.z > 0.f ? v.z : expm1f(v.z);
    v.w = v.w > 0.f ? v.w : expm1f(v.w);

    // node-local max over 256 features (2 warps)
    float m = fmaxf(fmaxf(v.x, v.y), fmaxf(v.z, v.w));
    m = wred_max(m);
    if (lane == 0) smax[warp] = m;
    __syncthreads();
    float mx = fmaxf(smax[2 * ng], smax[2 * ng + 1]);

    // node-local sum of exp
    float ex = expf(v.x - mx) + expf(v.y - mx) + expf(v.z - mx) + expf(v.w - mx);
    ex = wred_sum(ex);
    if (lane == 0) ssum[warp] = ex;
    __syncthreads();
    float lse = logf(ssum[2 * ng] + ssum[2 * ng + 1]) + mx;

    *(float4*)&out[(size_t)n * FO + fbase] =
        make_float4(v.x - lse, v.y - lse, v.z - lse, v.w - lse);
}

// ======================= launch (fork/join overlap) =======================
extern "C" void kernel_launch(void* const* d_in, const int* in_sizes, int n_in,
                              void* d_out, int out_size) {
    const float* x  = (const float*)d_in[0];
    const float* W  = (const float*)d_in[1];
    const float* a  = (const float*)d_in[2];
    const int*   ei = (const int*)d_in[3];
    const int*   row = ei;        // edge_index[0]
    const int*   col = ei + ER;   // edge_index[1]
    float* out = (float*)d_out;

    // Side stream + events (host objects only; never destroyed mid-capture).
    cudaStream_t s2;
    cudaStreamCreateWithFlags(&s2, cudaStreamNonBlocking);
    cudaEvent_t evFork, evJoin;
    cudaEventCreateWithFlags(&evFork, cudaEventDisableTiming);
    cudaEventCreateWithFlags(&evJoin, cudaEventDisableTiming);

    // main stream: init (zeroes srow/scol/cnt — needed by BOTH chains)
    init_kernel  <<<(NN + 255) / 256, 256>>>();
    cudaEventRecord(evFork, 0);

    // side stream: hist -> scan -> CSR fill (all GEMM-independent)
    cudaStreamWaitEvent(s2, evFork, 0);
    hist_kernel  <<<(ER + 255) / 256, 256, 0, s2>>>(row);
    scan_reduce  <<<SCAN_B, 256, 0, s2>>>();
    scan_partials<<<1, 256, 0, s2>>>();
    scan_write   <<<SCAN_B, 256, 0, s2>>>();
    fill_kernel  <<<(ER + 255) / 256, 256, 0, s2>>>(row, col);
    cudaEventRecord(evJoin, s2);

    // main stream: persistent GEMM runs concurrently with the side chain
    gemm_kernel  <<<GEMM_CTAS, 256>>>(x, W, a);

    // join: gather needs scores (GEMM) + CSR (side chain)
    cudaStreamWaitEvent(0, evJoin, 0);
    gather_final <<<NN / 4, 256>>>(out);
}